// round 16
// baseline (speedup 1.0000x reference)
#include <cuda_runtime.h>
#include <cuda_fp16.h>
#include <math.h>
#include <stdint.h>

#define Bb 16
#define Cc 256
#define Nn 4096
#define THREEC 768
#define NSPLIT 4

// -------- scratch (device globals; no allocs allowed) --------
__device__ float g_xnt[(size_t)Bb * Nn * Cc];     // GN output, [b][n][c]
__device__ float g_qkv[(size_t)Bb * THREEC * Nn]; // [b][o][n]; only k,v slots used
__device__ float g_qt[(size_t)Bb * Nn * Cc];      // q, [b][n][h*64+d], elu+1 applied
__device__ float g_attnt[(size_t)Bb * Nn * Cc];   // attn output, [b][n][c]
__device__ float g_kv[(size_t)NSPLIT * 64 * 4096];  // kvT partials [e][d]
__device__ float g_ks[(size_t)NSPLIT * 64 * 64];

__device__ __forceinline__ uint32_t smem_u32(const void* p) {
    uint32_t a;
    asm("{ .reg .u64 t; cvta.to.shared.u64 t, %1; cvt.u32.u64 %0, t; }" : "=r"(a) : "l"(p));
    return a;
}

#define CP16(saddr, gptr) \
    asm volatile("cp.async.cg.shared.global [%0], [%1], 16;" :: "r"(saddr), "l"(gptr))
#define CP_COMMIT() asm volatile("cp.async.commit_group;" ::: "memory")
#define CP_WAIT0()  asm volatile("cp.async.wait_group 0;" ::: "memory")
#define CP_WAIT1()  asm volatile("cp.async.wait_group 1;" ::: "memory")

__device__ __forceinline__ void mma_tf32(float c[4], uint32_t a0, uint32_t a1,
                                         uint32_t a2, uint32_t a3,
                                         uint32_t b0, uint32_t b1) {
    asm volatile(
        "mma.sync.aligned.m16n8k8.row.col.f32.tf32.tf32.f32 "
        "{%0,%1,%2,%3}, {%4,%5,%6,%7}, {%8,%9}, {%0,%1,%2,%3};"
        : "+f"(c[0]), "+f"(c[1]), "+f"(c[2]), "+f"(c[3])
        : "r"(a0), "r"(a1), "r"(a2), "r"(a3), "r"(b0), "r"(b1));
}

// ============================================================
// K1: GroupNorm, writes transposed g_xnt[b][n][c]
// ============================================================
__global__ __launch_bounds__(256) void gn_kernel(const float* __restrict__ x,
                                                 const float* __restrict__ gamma,
                                                 const float* __restrict__ beta) {
    const int b = blockIdx.x >> 5;
    const int g = blockIdx.x & 31;
    const int c0 = g * 8;
    const size_t base = ((size_t)b * Cc + c0) * Nn;
    const float4* x4 = (const float4*)(x + base);
    const int t = threadIdx.x;

    float s = 0.f, ss = 0.f;
    const int n4 = 8 * Nn / 4;
    #pragma unroll 4
    for (int i = t; i < n4; i += 256) {
        float4 v = x4[i];
        s  += v.x + v.y + v.z + v.w;
        ss += v.x * v.x + v.y * v.y + v.z * v.z + v.w * v.w;
    }
    __shared__ float red[64];
    #pragma unroll
    for (int o = 16; o; o >>= 1) {
        s  += __shfl_xor_sync(0xffffffffu, s, o);
        ss += __shfl_xor_sync(0xffffffffu, ss, o);
    }
    const int w = t >> 5;
    if ((t & 31) == 0) { red[w] = s; red[32 + w] = ss; }
    __syncthreads();
    if (t < 32) {
        s  = (t < 8) ? red[t] : 0.f;
        ss = (t < 8) ? red[32 + t] : 0.f;
        #pragma unroll
        for (int o = 4; o; o >>= 1) {
            s  += __shfl_xor_sync(0xffffffffu, s, o);
            ss += __shfl_xor_sync(0xffffffffu, ss, o);
        }
        if (t == 0) { red[0] = s; red[1] = ss; }
    }
    __syncthreads();
    const float inv = 1.f / (float)(8 * Nn);
    const float mean = red[0] * inv;
    const float var = red[1] * inv - mean * mean;
    const float rstd = rsqrtf(var + 1e-5f);

    float ga[8], be[8];
    #pragma unroll
    for (int j = 0; j < 8; j++) {
        ga[j] = gamma[c0 + j] * rstd;
        be[j] = beta[c0 + j] - mean * ga[j];
    }
    const float* xg = x + base;
    float* dst0 = g_xnt + (size_t)b * Nn * Cc + c0;
    for (int i = t; i < Nn; i += 256) {
        float v[8];
        #pragma unroll
        for (int j = 0; j < 8; j++)
            v[j] = __ldg(xg + (size_t)j * Nn + i) * ga[j] + be[j];
        float4* d = (float4*)(dst0 + (size_t)i * Cc);
        d[0] = make_float4(v[0], v[1], v[2], v[3]);
        d[1] = make_float4(v[4], v[5], v[6], v[7]);
    }
}

// ============================================================
// K2/K5: tf32 mma GEMM, cp.async 3-stage pipelined, BK=32.
// D[n,o] = sum_c A[n,c] * W[o,c]; CTA 128x128; warp tile 64x32.
// MODE 0: A=g_xnt. q blocks (o0<256): direct frag store -> g_qt[b][n][o], elu.
//         k,v blocks: transpose -> g_qkv[b][o][n], elu for o<512 (k only).
// MODE 1: A=g_attnt -> Yout[b][o][n], bias + residual.
// Dynamic smem: 3 stages x (A 128x36 + W 128x36) floats = 110592 B.
// ============================================================
#define ASTRIDE 36
#define CSTRIDE 129
#define STAGEF 9216   // floats per stage (2 * 128 * 36)

template <int MODE>
__global__ __launch_bounds__(256) void mma_gemm(const float* __restrict__ W,
                                                const float* __restrict__ bias,
                                                const float* __restrict__ resid,
                                                float* __restrict__ Yout) {
    extern __shared__ __align__(16) float dsm[];
    const int b = blockIdx.z;
    const int n0 = blockIdx.x * 128;
    const int o0 = blockIdx.y * 128;
    const float* Ag = (MODE == 0 ? g_xnt : g_attnt) + (size_t)b * Nn * Cc;

    const int t = threadIdx.x;
    const int l = t & 31;
    const int wid = t >> 5;
    const int wm = wid & 1;
    const int wn = wid >> 1;
    const int lc4 = t & 7;
    const int lr  = t >> 3;
    const uint32_t sb = smem_u32(dsm);

    float c[4][4][4] = {};

    auto prefetch = [&](int kt8, int stg) {
        const int kt = kt8 * 32;
        const uint32_t abase = sb + (uint32_t)stg * STAGEF * 4;
        const uint32_t wbase = abase + 4608 * 4;
        #pragma unroll
        for (int i = 0; i < 4; i++) {
            const int r = lr + i * 32;
            const uint32_t off = (uint32_t)(r * ASTRIDE + lc4 * 4) * 4;
            CP16(abase + off, Ag + (size_t)(n0 + r) * Cc + kt + lc4 * 4);
            CP16(wbase + off, W  + (size_t)(o0 + r) * Cc + kt + lc4 * 4);
        }
    };

    prefetch(0, 0); CP_COMMIT();
    prefetch(1, 1); CP_COMMIT();

    for (int kt8 = 0; kt8 < 8; kt8++) {
        if (kt8 < 7) CP_WAIT1(); else CP_WAIT0();
        __syncthreads();
        if (kt8 < 6) { prefetch(kt8 + 2, (kt8 + 2) % 3); CP_COMMIT(); }
        const uint32_t* Asu = (const uint32_t*)(dsm + (kt8 % 3) * STAGEF);
        const uint32_t* Wsu = Asu + 4608;
        #pragma unroll
        for (int ks = 0; ks < 4; ks++) {
            const int k = ks * 8;
            const int ar = wm * 64 + (l >> 2);
            const int ac = k + (l & 3);
            uint32_t a[4][4];
            #pragma unroll
            for (int mf = 0; mf < 4; mf++) {
                const int r0 = (ar + mf * 16) * ASTRIDE;
                a[mf][0] = Asu[r0 + ac];
                a[mf][1] = Asu[r0 + 8 * ASTRIDE + ac];
                a[mf][2] = Asu[r0 + ac + 4];
                a[mf][3] = Asu[r0 + 8 * ASTRIDE + ac + 4];
            }
            uint32_t bf[4][2];
            const int bn = wn * 32 + (l >> 2);
            #pragma unroll
            for (int nf = 0; nf < 4; nf++) {
                const int r0 = (bn + nf * 8) * ASTRIDE;
                bf[nf][0] = Wsu[r0 + ac];
                bf[nf][1] = Wsu[r0 + ac + 4];
            }
            #pragma unroll
            for (int mf = 0; mf < 4; mf++)
                #pragma unroll
                for (int nf = 0; nf < 4; nf++)
                    mma_tf32(c[mf][nf], a[mf][0], a[mf][1], a[mf][2], a[mf][3],
                             bf[nf][0], bf[nf][1]);
        }
    }
    __syncthreads();

    if (MODE == 0 && o0 < 256) {
        // q blocks: direct fragment store to g_qt[b][n][o], bias + elu+1
        float* Qt = g_qt + (size_t)b * Nn * Cc;
        #pragma unroll
        for (int mf = 0; mf < 4; mf++) {
            const int rn = n0 + wm * 64 + mf * 16 + (l >> 2);
            #pragma unroll
            for (int nf = 0; nf < 4; nf++) {
                const int col = o0 + wn * 32 + nf * 8 + (l & 3) * 2;
                const float b0 = __ldg(bias + col);
                const float b1 = __ldg(bias + col + 1);
                float v0 = c[mf][nf][0] + b0, v1 = c[mf][nf][1] + b1;
                float v2 = c[mf][nf][2] + b0, v3 = c[mf][nf][3] + b1;
                v0 = v0 > 0.f ? v0 + 1.f : expf(v0);
                v1 = v1 > 0.f ? v1 + 1.f : expf(v1);
                v2 = v2 > 0.f ? v2 + 1.f : expf(v2);
                v3 = v3 > 0.f ? v3 + 1.f : expf(v3);
                *(float2*)(Qt + (size_t)rn * Cc + col)       = make_float2(v0, v1);
                *(float2*)(Qt + (size_t)(rn + 8) * Cc + col) = make_float2(v2, v3);
            }
        }
        return;
    }

    // transpose epilogue via smem (fp32 Cs overlays the stages)
    float* const Cs = dsm;
    #pragma unroll
    for (int half = 0; half < 2; half++) {
        if (wm == half) {
            #pragma unroll
            for (int mf = 0; mf < 4; mf++) {
                const int row = mf * 16 + (l >> 2);
                #pragma unroll
                for (int nf = 0; nf < 4; nf++) {
                    const int col = wn * 32 + nf * 8 + (l & 3) * 2;
                    Cs[row * CSTRIDE + col]           = c[mf][nf][0];
                    Cs[row * CSTRIDE + col + 1]       = c[mf][nf][1];
                    Cs[(row + 8) * CSTRIDE + col]     = c[mf][nf][2];
                    Cs[(row + 8) * CSTRIDE + col + 1] = c[mf][nf][3];
                }
            }
        }
        __syncthreads();
        const int nl = t & 63;
        const int ol0 = t >> 6;
        const int n = n0 + half * 64 + nl;
        #pragma unroll
        for (int jj = 0; jj < 32; jj++) {
            const int o = ol0 + jj * 4;
            const int og = o0 + o;
            float v = Cs[nl * CSTRIDE + o] + __ldg(bias + og);
            if (MODE == 0) {
                if (og < 2 * Cc) v = v > 0.f ? v + 1.f : expf(v);  // k rows
                g_qkv[((size_t)b * THREEC + og) * Nn + n] = v;
            } else {
                v += __ldg(resid + ((size_t)b * Cc + og) * Nn + n);
                Yout[((size_t)b * Cc + og) * Nn + n] = v;
            }
        }
        __syncthreads();
    }
}

// ============================================================
// K3: kvT[e,d] = sum_n v[e,n] k[d,n] via tf32 mma (validated R6).
// ============================================================
__global__ __launch_bounds__(256) void kv_mma() {
    __shared__ __align__(16) float sm[2 * 2 * 64 * ASTRIDE];
    __shared__ float red[128];
    const int bh = blockIdx.x, sp = blockIdx.y;
    const int b = bh >> 2, h = bh & 3;
    const float* Vp = g_qkv + ((size_t)b * THREEC + 2 * Cc + h * 64) * Nn;
    const float* Kp = g_qkv + ((size_t)b * THREEC + Cc + h * 64) * Nn;
    const int t = threadIdx.x, l = t & 31, wid = t >> 5;
    const int wm = wid & 1, wn = wid >> 1;
    const uint32_t sb = smem_u32(sm);
    const int nbase = sp * 1024;

    float c[2][2][4] = {};
    float ksp = 0.f;

    auto prefetch = [&](int nt, int stg) {
        #pragma unroll
        for (int q = 0; q < 2; q++) {
            const int f = t + q * 256;
            const int r = f >> 3, c4 = f & 7;
            const uint32_t off = (uint32_t)(stg * 4608 + r * ASTRIDE + c4 * 4) * 4;
            CP16(sb + off,            Vp + (size_t)r * Nn + nbase + nt * 32 + c4 * 4);
            CP16(sb + off + 2304 * 4, Kp + (size_t)r * Nn + nbase + nt * 32 + c4 * 4);
        }
    };

    prefetch(0, 0);
    CP_COMMIT();

    for (int nt = 0; nt < 32; nt++) {
        if (nt < 31) { prefetch(nt + 1, (nt + 1) & 1); CP_COMMIT(); CP_WAIT1(); }
        else CP_WAIT0();
        __syncthreads();
        const float* Vs = sm + (nt & 1) * 4608;
        const float* Ks = Vs + 2304;
        const uint32_t* Vsu = (const uint32_t*)Vs;
        const uint32_t* Ksu = (const uint32_t*)Ks;
        #pragma unroll
        for (int ks8 = 0; ks8 < 4; ks8++) {
            const int k = ks8 * 8;
            const int ar = wm * 32 + (l >> 2);
            const int ac = k + (l & 3);
            uint32_t a[2][4];
            #pragma unroll
            for (int mf = 0; mf < 2; mf++) {
                const int r0 = (ar + mf * 16) * ASTRIDE;
                a[mf][0] = Vsu[r0 + ac];
                a[mf][1] = Vsu[r0 + 8 * ASTRIDE + ac];
                a[mf][2] = Vsu[r0 + ac + 4];
                a[mf][3] = Vsu[r0 + 8 * ASTRIDE + ac + 4];
            }
            uint32_t bf[2][2];
            const int bn = wn * 16 + (l >> 2);
            #pragma unroll
            for (int nf = 0; nf < 2; nf++) {
                const int r0 = (bn + nf * 8) * ASTRIDE;
                bf[nf][0] = Ksu[r0 + ac];
                bf[nf][1] = Ksu[r0 + ac + 4];
            }
            #pragma unroll
            for (int mf = 0; mf < 2; mf++)
                #pragma unroll
                for (int nf = 0; nf < 2; nf++)
                    mma_tf32(c[mf][nf], a[mf][0], a[mf][1], a[mf][2], a[mf][3],
                             bf[nf][0], bf[nf][1]);
        }
        if (t < 128) {
            const int row = t & 63, hf = t >> 6;
            #pragma unroll
            for (int q = 0; q < 16; q++) ksp += Ks[row * ASTRIDE + hf * 16 + q];
        }
        __syncthreads();
    }

    if (t < 128) red[t] = ksp;
    __syncthreads();
    if (t < 64) g_ks[((size_t)sp * 64 + bh) * 64 + t] = red[t] + red[t + 64];

    float* kvout = g_kv + ((size_t)sp * 64 + bh) * 4096;
    #pragma unroll
    for (int mf = 0; mf < 2; mf++) {
        const int re = wm * 32 + mf * 16 + (l >> 2);
        #pragma unroll
        for (int nf = 0; nf < 2; nf++) {
            const int cd = wn * 16 + nf * 8 + (l & 3) * 2;
            *(float2*)(kvout + (size_t)re * 64 + cd)       = make_float2(c[mf][nf][0], c[mf][nf][1]);
            *(float2*)(kvout + (size_t)(re + 8) * 64 + cd) = make_float2(c[mf][nf][2], c[mf][nf][3]);
        }
    }
}

// ============================================================
// K3b: reduce kv/ks splits into slot 0 (validated R6)
// ============================================================
__global__ __launch_bounds__(256) void kvreduce_kernel() {
    const int bh = blockIdx.x, cq = blockIdx.y;
    const int t = threadIdx.x;
    const int i = cq * 1024 + t * 4;
    float4 s = make_float4(0.f, 0.f, 0.f, 0.f);
    #pragma unroll
    for (int sp = 0; sp < NSPLIT; sp++) {
        const float4 v = *(const float4*)(g_kv + ((size_t)sp * 64 + bh) * 4096 + i);
        s.x += v.x; s.y += v.y; s.z += v.z; s.w += v.w;
    }
    *(float4*)(g_kv + (size_t)bh * 4096 + i) = s;
    if (cq == 0 && t < 64) {
        float ks = 0.f;
        #pragma unroll
        for (int sp = 0; sp < NSPLIT; sp++)
            ks += g_ks[((size_t)sp * 64 + bh) * 64 + t];
        g_ks[(size_t)bh * 64 + t] = ks;
    }
}

// ============================================================
// K4: out[e,n] = (sum_d kvT[e,d] q[d,n]) / (q·ks + eps), tf32 mma (validated R6).
// ============================================================
__global__ __launch_bounds__(256) void attn_mma() {
    __shared__ __align__(16) float kvs[64 * 68];
    __shared__ __align__(16) float qs[64 * 68];   // reused as output staging
    __shared__ float kss[64], sden[64];
    const int bh = blockIdx.x, b = bh >> 2, h = bh & 3;
    const int n0 = blockIdx.y * 64;
    const int t = threadIdx.x, l = t & 31, wid = t >> 5;
    const int wm = wid & 1, wn = wid >> 1;

    for (int i = t; i < 4096; i += 256)
        kvs[(i >> 6) * 68 + (i & 63)] = g_kv[(size_t)bh * 4096 + i];
    if (t < 64) kss[t] = g_ks[(size_t)bh * 64 + t];
    const float* Qt = g_qt + ((size_t)b * Nn + n0) * Cc + h * 64;
    for (int f = t; f < 1024; f += 256) {
        const int r = f >> 4, c4 = f & 15;
        *(float4*)&qs[r * 68 + c4 * 4] = *(const float4*)(Qt + (size_t)r * Cc + c4 * 4);
    }
    __syncthreads();
    if (t < 64) {
        float den = 0.f;
        #pragma unroll
        for (int d = 0; d < 64; d++) den += qs[t * 68 + d] * kss[d];
        sden[t] = 1.f / (den + 1e-6f);
    }
    __syncthreads();

    float c[2][2][4] = {};
    const uint32_t* Au = (const uint32_t*)kvs;
    const uint32_t* Bu = (const uint32_t*)qs;
    #pragma unroll
    for (int ks8 = 0; ks8 < 8; ks8++) {
        const int k = ks8 * 8;
        const int ar = wm * 32 + (l >> 2);
        const int ac = k + (l & 3);
        uint32_t a[2][4];
        #pragma unroll
        for (int mf = 0; mf < 2; mf++) {
            const int r0 = (ar + mf * 16) * 68;
            a[mf][0] = Au[r0 + ac];
            a[mf][1] = Au[r0 + 8 * 68 + ac];
            a[mf][2] = Au[r0 + ac + 4];
            a[mf][3] = Au[r0 + 8 * 68 + ac + 4];
        }
        uint32_t bf[2][2];
        const int bn = wn * 16 + (l >> 2);
        #pragma unroll
        for (int nf = 0; nf < 2; nf++) {
            const int r0 = (bn + nf * 8) * 68;
            bf[nf][0] = Bu[r0 + ac];
            bf[nf][1] = Bu[r0 + ac + 4];
        }
        #pragma unroll
        for (int mf = 0; mf < 2; mf++)
            #pragma unroll
            for (int nf = 0; nf < 2; nf++)
                mma_tf32(c[mf][nf], a[mf][0], a[mf][1], a[mf][2], a[mf][3],
                         bf[nf][0], bf[nf][1]);
    }
    __syncthreads();   // qs reads done; reuse as Cs[n][e]

    #pragma unroll
    for (int mf = 0; mf < 2; mf++) {
        const int re = wm * 32 + mf * 16 + (l >> 2);
        #pragma unroll
        for (int nf = 0; nf < 2; nf++) {
            const int cn = wn * 16 + nf * 8 + (l & 3) * 2;
            const float s0 = sden[cn], s1 = sden[cn + 1];
            qs[cn * 68 + re]           = c[mf][nf][0] * s0;
            qs[(cn + 1) * 68 + re]     = c[mf][nf][1] * s1;
            qs[cn * 68 + re + 8]       = c[mf][nf][2] * s0;
            qs[(cn + 1) * 68 + re + 8] = c[mf][nf][3] * s1;
        }
    }
    __syncthreads();

    float* Op = g_attnt + ((size_t)b * Nn + n0) * Cc + h * 64;
    #pragma unroll
    for (int p = 0; p < 4; p++) {
        const int n = (t >> 4) + p * 16;
        const int e4 = t & 15;
        *(float4*)(Op + (size_t)n * Cc + e4 * 4) = *(const float4*)&qs[n * 68 + e4 * 4];
    }
}

// ============================================================
extern "C" void kernel_launch(void* const* d_in, const int* in_sizes, int n_in,
                              void* d_out, int out_size) {
    const float* x     = (const float*)d_in[0];
    const float* gamma = (const float*)d_in[1];
    const float* beta  = (const float*)d_in[2];
    const float* w_qkv = (const float*)d_in[3];
    const float* b_qkv = (const float*)d_in[4];
    const float* w_out = (const float*)d_in[5];
    const float* b_out = (const float*)d_in[6];
    float* out = (float*)d_out;

    const int dyn = STAGEF * 3 * 4;  // 110592 B
    cudaFuncSetAttribute(mma_gemm<0>, cudaFuncAttributeMaxDynamicSharedMemorySize, dyn);
    cudaFuncSetAttribute(mma_gemm<1>, cudaFuncAttributeMaxDynamicSharedMemorySize, dyn);

    gn_kernel<<<Bb * 32, 256>>>(x, gamma, beta);

    dim3 g2(Nn / 128, THREEC / 128, Bb);
    mma_gemm<0><<<g2, 256, dyn>>>(w_qkv, b_qkv, nullptr, nullptr);

    dim3 g3(Bb * 4, NSPLIT);
    kv_mma<<<g3, 256>>>();

    dim3 g3b(Bb * 4, 4);
    kvreduce_kernel<<<g3b, 256>>>();

    dim3 g4(Bb * 4, Nn / 64);
    attn_mma<<<g4, 256>>>();

    dim3 g5(Nn / 128, Cc / 128, Bb);
    mma_gemm<1><<<g5, 256, dyn>>>(w_out, b_out, x, out);
}